// round 15
// baseline (speedup 1.0000x reference)
#include <cuda_runtime.h>
#include <cuda_fp16.h>
#include <cstdint>

#define THREADS 256
#define TILE_M 32

// ---- folded constants ----
#define PW0F 0.08838834764831845f   // sqrt(1/128)
#define C0BF 0.05103103630798288f   // PW0/sqrt(3)
#define C1F  0.08838834764831845f   // sqrt(3/128)/sqrt(3) = PW0
#define C2F  0.7071067811865476f    // sqrt(3/64)/sqrt(6)*8 = 1/sqrt(2)

// ---- smem layout (byte offsets), ~103.4 KB -> 2 CTAs / SM ----
// Weights: 5 fp16 tiles [64k x 64n], 128B rows, swizzled. 0=Wss 1=Wvv0 2=Wsv 3=Wvs 4=Wvv1
// A ping/pong: 6 fp16 buffers [32r x 64k] = 4096B each -> 24576B per buffer
// Stage: 8 rows x 452 f32 (epilogue quarter) - dedicated region
// X2 ping/pong: 32 * float4 each
#define SM_W     0
#define SM_A0    40960
#define SM_A1    65536
#define SM_STG   90112
#define SM_X2    104576     // 2 x 512B
#define SM_BIAS  105600     // 64 * f32
#define SM_TOTAL 105856
#define STG_STRIDE 452      // multiple of 4 (float4 copy-out alignment)

#define SWZ(o) ((o) ^ (((o) >> 3) & 0x70))

// ================= helpers =================
static __device__ __forceinline__ uint32_t smem_u32(const void* p) {
    uint32_t a;
    asm("{ .reg .u64 t; cvta.to.shared.u64 t, %1; cvt.u32.u64 %0, t; }" : "=r"(a) : "l"(p));
    return a;
}
static __device__ __forceinline__ void ldsm4(uint32_t* r, uint32_t addr) {
    asm volatile("ldmatrix.sync.aligned.m8n8.x4.shared.b16 {%0,%1,%2,%3}, [%4];"
                 : "=r"(r[0]), "=r"(r[1]), "=r"(r[2]), "=r"(r[3]) : "r"(addr));
}
static __device__ __forceinline__ void ldsm4t(uint32_t* r, uint32_t addr) {
    asm volatile("ldmatrix.sync.aligned.m8n8.x4.trans.shared.b16 {%0,%1,%2,%3}, [%4];"
                 : "=r"(r[0]), "=r"(r[1]), "=r"(r[2]), "=r"(r[3]) : "r"(addr));
}
static __device__ __forceinline__ void mma16816h(float* d, const uint32_t* a, uint32_t b0, uint32_t b1) {
    asm volatile("mma.sync.aligned.m16n8k16.row.col.f32.f16.f16.f32 "
                 "{%0,%1,%2,%3}, {%4,%5,%6,%7}, {%8,%9}, {%0,%1,%2,%3};"
                 : "+f"(d[0]), "+f"(d[1]), "+f"(d[2]), "+f"(d[3])
                 : "r"(a[0]), "r"(a[1]), "r"(a[2]), "r"(a[3]), "r"(b0), "r"(b1));
}
static __device__ __forceinline__ void dualmma(float d[2][4], const uint32_t* a, const uint32_t* B) {
    #pragma unroll
    for (int nb = 0; nb < 2; nb++)
        mma16816h(d[nb], a, B[2 * nb], B[2 * nb + 1]);
}
// fp32 pair -> packed fp16 at swizzled offset
static __device__ __forceinline__ void put_h(char* smem, uint32_t base, uint32_t off, float v0, float v1) {
    __half h0 = __float2half_rn(v0);
    __half h1 = __float2half_rn(v1);
    uint32_t hp = (uint32_t)__half_as_ushort(h0) | ((uint32_t)__half_as_ushort(h1) << 16);
    *(uint32_t*)(smem + base + SWZ(off)) = hp;
}
static __device__ __forceinline__ void stg_cs4(float* p, float4 v) {
    asm volatile("st.global.cs.v4.f32 [%0], {%1,%2,%3,%4};"
                 :: "l"(p), "f"(v.x), "f"(v.y), "f"(v.z), "f"(v.w) : "memory");
}

// build 6 A channels for one tile into the given A buffer; also stage x2 rows
static __device__ __forceinline__ void build_tile(
    char* smem, uint32_t abase, uint32_t x2off,
    const float* __restrict__ x1, const float* __restrict__ x2,
    int row0, int nrows, int tid)
{
    #pragma unroll
    for (int it = 0; it < 4; it++) {
        int idx = it * THREADS + tid;            // 0..1023
        int row = idx >> 5, kp = idx & 31;
        int rg = row0 + row; if (rg >= nrows) rg = nrows - 1;
        const float* xr = x1 + (size_t)rg * 256;
        float2 xs = *(const float2*)(xr + 2 * kp);
        float2 f0 = *(const float2*)(xr + 64 + 6 * kp);
        float2 f1 = *(const float2*)(xr + 66 + 6 * kp);
        float2 f2 = *(const float2*)(xr + 68 + 6 * kp);
        float4 q = __ldg((const float4*)(x2 + (size_t)4 * rg));
        if (kp == 0) *(float4*)(smem + x2off + row * 16) = q;
        uint32_t off = (uint32_t)(row * 128 + kp * 4);
        float sc = PW0F * q.x;
        put_h(smem, abase + 0 * 4096, off, sc * xs.x, sc * xs.y);
        float d0 = fmaf(f0.x, q.y, fmaf(f0.y, q.z, f1.x * q.w));
        float d1 = fmaf(f1.y, q.y, fmaf(f2.x, q.z, f2.y * q.w));
        put_h(smem, abase + 1 * 4096, off, C0BF * d0, C0BF * d1);
        put_h(smem, abase + 2 * 4096, off, xs.x, xs.y);
        put_h(smem, abase + 3 * 4096, off, f0.x, f1.y);
        put_h(smem, abase + 4 * 4096, off, f0.y, f2.x);
        put_h(smem, abase + 5 * 4096, off, f1.x, f2.y);
    }
}

__global__ __launch_bounds__(THREADS, 2)
void o3tp_mma9_kernel(const float* __restrict__ x1, const float* __restrict__ x2,
                      const float* __restrict__ w_ss, const float* __restrict__ w_vv0,
                      const float* __restrict__ w_sv, const float* __restrict__ w_vs,
                      const float* __restrict__ w_vv1, const float* __restrict__ bias,
                      float* __restrict__ out, int nrows)
{
    extern __shared__ char smem[];
    const int tid = threadIdx.x;
    const int lane = tid & 31;
    const int wid = tid >> 5;
    const int rq = wid & 1;        // row block: rows 16*rq .. +16 (of 32)
    const int nh = wid >> 1;       // col block: cols 16*nh .. +16
    const uint32_t smb = smem_u32(smem);

    // ---- weight prep: [k][n] fp16, swizzled ----
    {
        const float* wsrc[5] = { w_ss, w_vv0, w_sv, w_vs, w_vv1 };
        #pragma unroll
        for (int m = 0; m < 5; m++) {
            uint32_t base = SM_W + (uint32_t)m * 8192;
            #pragma unroll
            for (int it = 0; it < 8; it++) {
                int idx = it * THREADS + tid;         // 0..2047
                int k = idx >> 5, np = idx & 31;
                float2 w2 = *(const float2*)(wsrc[m] + k * 64 + 2 * np);
                put_h(smem, base, (uint32_t)(k * 128 + np * 4), w2.x, w2.y);
            }
        }
        if (tid < 64) *(float*)(smem + SM_BIAS + tid * 4) = bias[tid];
    }

    // ---- per-lane constant address pieces ----
    const int t4 = lane >> 3;
    const int arow = 16 * rq + ((t4 & 1) << 3) + (lane & 7);       // 0..31
    const uint32_t a_rb  = (uint32_t)arow * 128;
    const uint32_t a_kx  = (uint32_t)(arow & 7) << 4;
    const uint32_t a_kb0 = (uint32_t)(t4 >> 1) << 4;
    const int brow_l = ((t4 & 1) << 3) + (lane & 7);
    const uint32_t b_cb = (uint32_t)(2 * (16 * nh + ((t4 >> 1) << 3)));
    const uint32_t b_kx = (uint32_t)(lane & 7) << 4;

    const int ntiles = (nrows + TILE_M - 1) / TILE_M;
    const int g = lane >> 2, tq = lane & 3;
    float* stg = (float*)(smem + SM_STG);
    const float* bias_s = (const float*)(smem + SM_BIAS);

    // ---- prologue: build first tile into buffer 0 ----
    int tile = blockIdx.x;
    if (tile < ntiles)
        build_tile(smem, SM_A0, SM_X2, x1, x2, tile * TILE_M, nrows, tid);
    int buf = 0;

    for (; tile < ntiles; tile += gridDim.x) {
        const int row0 = tile * TILE_M;
        const uint32_t abase = buf ? SM_A1 : SM_A0;
        const uint32_t x2off = SM_X2 + (uint32_t)buf * 512;
        __syncthreads();   // A[buf] + X2[buf] visible; stage region free

        // ---- GEMMs on A[buf]: d0=out0(merged) d1=Ysv d2-4=Yv_i d5-7=Yw_i ----
        float d[8][2][4];
        #pragma unroll
        for (int q8 = 0; q8 < 8; q8++)
            #pragma unroll
            for (int nb = 0; nb < 2; nb++)
                #pragma unroll
                for (int e = 0; e < 4; e++) d[q8][nb][e] = 0.0f;

        #pragma unroll
        for (int ks = 0; ks < 4; ks++) {
            const uint32_t a_koff = (32u * ks + a_kb0) ^ a_kx;
            const uint32_t b_base = (uint32_t)(16 * ks + brow_l) * 128 + (b_cb ^ b_kx);
            uint32_t Ax[4], Bh[4];

            ldsm4(Ax, smb + abase + 0 * 4096 + a_rb + a_koff);
            ldsm4t(Bh, smb + SM_W + 0 * 8192 + b_base);
            dualmma(d[0], Ax, Bh);

            ldsm4(Ax, smb + abase + 1 * 4096 + a_rb + a_koff);
            ldsm4t(Bh, smb + SM_W + 1 * 8192 + b_base);
            dualmma(d[0], Ax, Bh);

            ldsm4(Ax, smb + abase + 2 * 4096 + a_rb + a_koff);
            ldsm4t(Bh, smb + SM_W + 2 * 8192 + b_base);
            dualmma(d[1], Ax, Bh);

            uint32_t Vh[4], Wh[4];
            ldsm4t(Vh, smb + SM_W + 3 * 8192 + b_base);
            ldsm4t(Wh, smb + SM_W + 4 * 8192 + b_base);
            #pragma unroll
            for (int j = 0; j < 3; j++) {
                ldsm4(Ax, smb + abase + (uint32_t)(3 + j) * 4096 + a_rb + a_koff);
                dualmma(d[2 + j], Ax, Vh);
                dualmma(d[5 + j], Ax, Wh);
            }
        }

        // ---- build next tile into alt buffer (LDG latency hidden by epilogue) ----
        {
            int tnext = tile + gridDim.x;
            if (tnext < ntiles) {
                build_tile(smem, buf ? SM_A0 : SM_A1, SM_X2 + (uint32_t)(buf ^ 1) * 512,
                           x1, x2, tnext * TILE_M, nrows, tid);
                // L2 prefetch two tiles ahead
                int tpf = tile + 2 * gridDim.x;
                if (tpf < ntiles) {
                    int r = tpf * TILE_M + (tid >> 3);
                    if (r < nrows) {
                        const float* p = x1 + (size_t)r * 256 + (tid & 7) * 32;
                        asm volatile("prefetch.global.L2 [%0];" :: "l"(p));
                    }
                }
            }
        }

        // ---- epilogue in four 8-row quarters (dedicated stage region) ----
        #pragma unroll 1
        for (int qt = 0; qt < 4; qt++) {
            const int qrq = qt >> 1, qhh = qt & 1;
            if (rq == qrq) {
                int rt = 16 * qrq + 8 * qhh + g;               // row in tile
                float4 q = *(const float4*)(smem + x2off + rt * 16);
                float x2s = q.x, v0 = q.y, v1 = q.z, v2 = q.w;
                float* sr = stg + g * STG_STRIDE;
                #pragma unroll
                for (int nt = 0; nt < 2; nt++) {
                    int cc0 = 16 * nh + 8 * nt + 2 * tq;
                    float o0[2], o1[6], o2[6];
                    #pragma unroll
                    for (int e = 0; e < 2; e++) {
                        int ri = 2 * qhh + e;
                        float Ysv = d[1][nt][ri];
                        float Yv0 = d[2][nt][ri], Yv1 = d[3][nt][ri], Yv2 = d[4][nt][ri];
                        float Yw0 = d[5][nt][ri], Yw1 = d[6][nt][ri], Yw2 = d[7][nt][ri];
                        o0[e] = d[0][nt][ri] + bias_s[cc0 + e];
                        o1[3 * e + 0] = C1F * fmaf(v0, Ysv, x2s * Yv0);
                        o1[3 * e + 1] = C1F * fmaf(v1, Ysv, x2s * Yv1);
                        o1[3 * e + 2] = C1F * fmaf(v2, Ysv, x2s * Yv2);
                        o2[3 * e + 0] = C2F * (Yw1 * v2 - Yw2 * v1);
                        o2[3 * e + 1] = C2F * (Yw2 * v0 - Yw0 * v2);
                        o2[3 * e + 2] = C2F * (Yw0 * v1 - Yw1 * v0);
                    }
                    *(float2*)(sr + cc0) = make_float2(o0[0], o0[1]);
                    float* p1 = sr + 64 + 3 * cc0;
                    *(float2*)(p1 + 0) = make_float2(o1[0], o1[1]);
                    *(float2*)(p1 + 2) = make_float2(o1[2], o1[3]);
                    *(float2*)(p1 + 4) = make_float2(o1[4], o1[5]);
                    float* p2 = sr + 256 + 3 * cc0;
                    *(float2*)(p2 + 0) = make_float2(o2[0], o2[1]);
                    *(float2*)(p2 + 2) = make_float2(o2[2], o2[3]);
                    *(float2*)(p2 + 4) = make_float2(o2[4], o2[5]);
                }
            }
            __syncthreads();
            // coalesced streaming copy-out: 8 rows x 448 f32 (896 float4)
            #pragma unroll
            for (int i = 0; i < 4; i++) {
                int f = i * THREADS + tid;
                if (f < 896) {
                    int r = f / 112, j = (f % 112) * 4;
                    float4 v = *(const float4*)(stg + r * STG_STRIDE + j);
                    int rg = row0 + 16 * qrq + 8 * qhh + r;
                    if (rg < nrows) stg_cs4(out + (size_t)rg * 448 + j, v);
                }
            }
            if (qt < 3) __syncthreads();   // last quarter's reuse covered by loop-top sync
        }
        buf ^= 1;
    }
}

extern "C" void kernel_launch(void* const* d_in, const int* in_sizes, int n_in,
                              void* d_out, int out_size)
{
    const float* x1    = (const float*)d_in[0];
    const float* x2    = (const float*)d_in[1];
    const float* w_ss  = (const float*)d_in[2];
    const float* w_vv0 = (const float*)d_in[3];
    const float* w_sv  = (const float*)d_in[4];
    const float* w_vs  = (const float*)d_in[5];
    const float* w_vv1 = (const float*)d_in[6];
    const float* bias  = (const float*)d_in[7];

    int nrows = in_sizes[0] / 256;
    int ntiles = (nrows + TILE_M - 1) / TILE_M;

    cudaFuncSetAttribute(o3tp_mma9_kernel, cudaFuncAttributeMaxDynamicSharedMemorySize, SM_TOTAL);

    int sm_count = 148;
    cudaDeviceGetAttribute(&sm_count, cudaDevAttrMultiProcessorCount, 0);
    int grid = 2 * sm_count;
    if (grid > ntiles) grid = ntiles;
    if (grid < 1) grid = 1;

    o3tp_mma9_kernel<<<grid, THREADS, SM_TOTAL>>>(
        x1, x2, w_ss, w_vv0, w_sv, w_vs, w_vv1, bias, (float*)d_out, nrows);
}

// round 16
// speedup vs baseline: 1.6312x; 1.6312x over previous
#include <cuda_runtime.h>
#include <cuda_fp16.h>
#include <cstdint>

#define THREADS 256
#define TILE_M 16

// ---- folded constants ----
#define PW0F 0.08838834764831845f   // sqrt(1/128)            -> folded into Wss
#define C0BF 0.05103103630798288f   // PW0/sqrt(3)            -> folded into Wvv0
#define C1F  0.08838834764831845f   // sqrt(3/128)/sqrt(3)    -> folded into Wsv, Wvs
#define C2F  0.7071067811865476f    // sqrt(3/64)/sqrt(6)*8   -> folded into Wvv1

// ---- smem layout (byte offsets), ~66.6 KB -> 3 CTAs / SM ----
// Weights: 5 fp16 tiles [64k x 64n] (consts pre-folded), 128B rows, swizzled.
//   0=Wss' 1=Wvv0' 2=Wsv' 3=Wvs' 4=Wvv1'
// A: 6 fp16 buffers [16r x 64k] = 2048B each. ch: 0=x2s*xs 1=dot 2=xs 3=a0 4=a1 5=a2
// Stage: 8 rows x 452 f32 (dedicated)
#define SM_W     0
#define SM_A     40960
#define SM_STG   53248
#define SM_X2    67712      // 16 * float4
#define SM_BIAS  67968      // 64 * f32
#define SM_TOTAL 68224
#define STG_STRIDE 452      // multiple of 4 (float4 copy-out alignment)

#define SWZ(o) ((o) ^ (((o) >> 3) & 0x70))

// ================= helpers =================
static __device__ __forceinline__ uint32_t smem_u32(const void* p) {
    uint32_t a;
    asm("{ .reg .u64 t; cvta.to.shared.u64 t, %1; cvt.u32.u64 %0, t; }" : "=r"(a) : "l"(p));
    return a;
}
static __device__ __forceinline__ void ldsm4(uint32_t* r, uint32_t addr) {
    asm volatile("ldmatrix.sync.aligned.m8n8.x4.shared.b16 {%0,%1,%2,%3}, [%4];"
                 : "=r"(r[0]), "=r"(r[1]), "=r"(r[2]), "=r"(r[3]) : "r"(addr));
}
static __device__ __forceinline__ void ldsm2t(uint32_t* r, uint32_t addr) {
    asm volatile("ldmatrix.sync.aligned.m8n8.x2.trans.shared.b16 {%0,%1}, [%2];"
                 : "=r"(r[0]), "=r"(r[1]) : "r"(addr));
}
static __device__ __forceinline__ void mma16816h(float* d, const uint32_t* a, uint32_t b0, uint32_t b1) {
    asm volatile("mma.sync.aligned.m16n8k16.row.col.f32.f16.f16.f32 "
                 "{%0,%1,%2,%3}, {%4,%5,%6,%7}, {%8,%9}, {%0,%1,%2,%3};"
                 : "+f"(d[0]), "+f"(d[1]), "+f"(d[2]), "+f"(d[3])
                 : "r"(a[0]), "r"(a[1]), "r"(a[2]), "r"(a[3]), "r"(b0), "r"(b1));
}
// fp32 pair -> packed fp16 at swizzled offset
static __device__ __forceinline__ void put_h(char* smem, uint32_t base, uint32_t off, float v0, float v1) {
    __half h0 = __float2half_rn(v0);
    __half h1 = __float2half_rn(v1);
    uint32_t hp = (uint32_t)__half_as_ushort(h0) | ((uint32_t)__half_as_ushort(h1) << 16);
    *(uint32_t*)(smem + base + SWZ(off)) = hp;
}
static __device__ __forceinline__ void stg_cs4(float* p, float4 v) {
    asm volatile("st.global.cs.v4.f32 [%0], {%1,%2,%3,%4};"
                 :: "l"(p), "f"(v.x), "f"(v.y), "f"(v.z), "f"(v.w) : "memory");
}

__global__ __launch_bounds__(THREADS, 3)
void o3tp_mma10_kernel(const float* __restrict__ x1, const float* __restrict__ x2,
                       const float* __restrict__ w_ss, const float* __restrict__ w_vv0,
                       const float* __restrict__ w_sv, const float* __restrict__ w_vs,
                       const float* __restrict__ w_vv1, const float* __restrict__ bias,
                       float* __restrict__ out, int nrows)
{
    extern __shared__ char smem[];
    const int tid = threadIdx.x;
    const int lane = tid & 31;
    const int nw = tid >> 5;       // warp owns cols 8*nw .. 8*nw+7, all 16 rows
    const uint32_t smb = smem_u32(smem);

    // ---- weight prep: [k][n] fp16, swizzled, constants folded ----
    {
        const float* wsrc[5] = { w_ss, w_vv0, w_sv, w_vs, w_vv1 };
        const float wscl[5] = { PW0F, C0BF, C1F, C1F, C2F };
        #pragma unroll
        for (int m = 0; m < 5; m++) {
            uint32_t base = SM_W + (uint32_t)m * 8192;
            float s = wscl[m];
            #pragma unroll
            for (int it = 0; it < 8; it++) {
                int idx = it * THREADS + tid;         // 0..2047
                int k = idx >> 5, np = idx & 31;
                float2 w2 = *(const float2*)(wsrc[m] + k * 64 + 2 * np);
                put_h(smem, base, (uint32_t)(k * 128 + np * 4), s * w2.x, s * w2.y);
            }
        }
        if (tid < 64) *(float*)(smem + SM_BIAS + tid * 4) = bias[tid];
    }
    __syncthreads();

    // ---- per-lane constant address pieces ----
    const int t4 = lane >> 3;
    const int arow = ((t4 & 1) << 3) + (lane & 7);     // 0..15
    const uint32_t a_rb  = (uint32_t)arow * 128;
    const uint32_t a_kx  = (uint32_t)(arow & 7) << 4;
    const uint32_t a_kb0 = (uint32_t)(t4 >> 1) << 4;
    const uint32_t b_krl = (uint32_t)(lane & 15);      // k row within 16 (lanes 0-15 used)
    const uint32_t b_cx  = ((uint32_t)(16 * nw)) ^ ((uint32_t)(lane & 7) << 4);

    const int ntiles = (nrows + TILE_M - 1) / TILE_M;
    const int g = lane >> 2, tq = lane & 3;
    float* stg = (float*)(smem + SM_STG);
    const float* bias_s = (const float*)(smem + SM_BIAS);

    for (int tile = blockIdx.x; tile < ntiles; tile += gridDim.x) {
        const int row0 = tile * TILE_M;

        // ---- L2 prefetch next tile's x1 (16 rows x 8 lines) ----
        {
            int tnext = tile + gridDim.x;
            if (tnext < ntiles && (tid & 15) < 8) {
                int r = tnext * TILE_M + (tid >> 4);
                if (r < nrows) {
                    const float* p = x1 + (size_t)r * 256 + (tid & 15) * 32;
                    asm volatile("prefetch.global.L2 [%0];" :: "l"(p));
                }
            }
        }

        // ---- build 6 A channels, fp16 ----
        #pragma unroll
        for (int it = 0; it < 2; it++) {
            int idx = it * THREADS + tid;            // 0..511
            int row = idx >> 5, kp = idx & 31;
            int rg = row0 + row; if (rg >= nrows) rg = nrows - 1;
            const float* xr = x1 + (size_t)rg * 256;
            float2 xs = *(const float2*)(xr + 2 * kp);
            float2 f0 = *(const float2*)(xr + 64 + 6 * kp);
            float2 f1 = *(const float2*)(xr + 66 + 6 * kp);
            float2 f2 = *(const float2*)(xr + 68 + 6 * kp);
            float4 q = __ldg((const float4*)(x2 + (size_t)4 * rg));
            if (kp == 0) *(float4*)(smem + SM_X2 + row * 16) = q;
            uint32_t off = (uint32_t)(row * 128 + kp * 4);
            put_h(smem, SM_A + 0 * 2048, off, q.x * xs.x, q.x * xs.y);   // x2s gate (PW0 in W)
            float d0 = fmaf(f0.x, q.y, fmaf(f0.y, q.z, f1.x * q.w));
            float d1 = fmaf(f1.y, q.y, fmaf(f2.x, q.z, f2.y * q.w));
            put_h(smem, SM_A + 1 * 2048, off, d0, d1);                   // dot (C0B in W)
            put_h(smem, SM_A + 2 * 2048, off, xs.x, xs.y);
            put_h(smem, SM_A + 3 * 2048, off, f0.x, f1.y);
            put_h(smem, SM_A + 4 * 2048, off, f0.y, f2.x);
            put_h(smem, SM_A + 5 * 2048, off, f1.x, f2.y);
        }
        __syncthreads();

        // ---- GEMMs: d0=out0(merged) d1=Ysv' d2-4=Yv_i' d5-7=Yw_i' ----
        float d[8][4];
        #pragma unroll
        for (int q8 = 0; q8 < 8; q8++)
            #pragma unroll
            for (int e = 0; e < 4; e++) d[q8][e] = 0.0f;

        #pragma unroll
        for (int ks = 0; ks < 4; ks++) {
            const uint32_t a_koff = (32u * ks + a_kb0) ^ a_kx;
            const uint32_t b_row = (uint32_t)(16 * ks + b_krl) * 128 + b_cx;
            uint32_t Ax[4], B[2];

            ldsm4(Ax, smb + SM_A + 0 * 2048 + a_rb + a_koff);
            ldsm2t(B, smb + SM_W + 0 * 8192 + b_row);
            mma16816h(d[0], Ax, B[0], B[1]);

            ldsm4(Ax, smb + SM_A + 1 * 2048 + a_rb + a_koff);
            ldsm2t(B, smb + SM_W + 1 * 8192 + b_row);
            mma16816h(d[0], Ax, B[0], B[1]);

            ldsm4(Ax, smb + SM_A + 2 * 2048 + a_rb + a_koff);
            ldsm2t(B, smb + SM_W + 2 * 8192 + b_row);
            mma16816h(d[1], Ax, B[0], B[1]);

            uint32_t V[2], W2[2];
            ldsm2t(V, smb + SM_W + 3 * 8192 + b_row);
            ldsm2t(W2, smb + SM_W + 4 * 8192 + b_row);
            #pragma unroll
            for (int j = 0; j < 3; j++) {
                ldsm4(Ax, smb + SM_A + (uint32_t)(3 + j) * 2048 + a_rb + a_koff);
                mma16816h(d[2 + j], Ax, V[0], V[1]);
                mma16816h(d[5 + j], Ax, W2[0], W2[1]);
            }
        }

        // ---- epilogue in two 8-row halves (all warps active each half) ----
        #pragma unroll 1
        for (int hh = 0; hh < 2; hh++) {
            {
                int rt = g + 8 * hh;                         // row in tile
                float4 q = *(const float4*)(smem + SM_X2 + rt * 16);
                float x2s = q.x, v0 = q.y, v1 = q.z, v2 = q.w;
                float* sr = stg + g * STG_STRIDE;
                int cc0 = 8 * nw + 2 * tq;
                float o0[2], o1[6], o2[6];
                #pragma unroll
                for (int e = 0; e < 2; e++) {
                    int ri = 2 * hh + e;
                    float Ysv = d[1][ri];
                    float Yv0 = d[2][ri], Yv1 = d[3][ri], Yv2 = d[4][ri];
                    float Yw0 = d[5][ri], Yw1 = d[6][ri], Yw2 = d[7][ri];
                    o0[e] = d[0][ri] + bias_s[cc0 + e];
                    o1[3 * e + 0] = fmaf(v0, Ysv, x2s * Yv0);
                    o1[3 * e + 1] = fmaf(v1, Ysv, x2s * Yv1);
                    o1[3 * e + 2] = fmaf(v2, Ysv, x2s * Yv2);
                    o2[3 * e + 0] = Yw1 * v2 - Yw2 * v1;
                    o2[3 * e + 1] = Yw2 * v0 - Yw0 * v2;
                    o2[3 * e + 2] = Yw0 * v1 - Yw1 * v0;
                }
                *(float2*)(sr + cc0) = make_float2(o0[0], o0[1]);
                float* p1 = sr + 64 + 3 * cc0;
                *(float2*)(p1 + 0) = make_float2(o1[0], o1[1]);
                *(float2*)(p1 + 2) = make_float2(o1[2], o1[3]);
                *(float2*)(p1 + 4) = make_float2(o1[4], o1[5]);
                float* p2 = sr + 256 + 3 * cc0;
                *(float2*)(p2 + 0) = make_float2(o2[0], o2[1]);
                *(float2*)(p2 + 2) = make_float2(o2[2], o2[3]);
                *(float2*)(p2 + 4) = make_float2(o2[4], o2[5]);
            }
            __syncthreads();
            // coalesced streaming copy-out: 8 rows x 448 f32 (896 float4)
            #pragma unroll
            for (int i = 0; i < 4; i++) {
                int f = i * THREADS + tid;
                if (f < 896) {
                    int r = f / 112, j = (f % 112) * 4;
                    float4 v = *(const float4*)(stg + r * STG_STRIDE + j);
                    int rg = row0 + 8 * hh + r;
                    if (rg < nrows) stg_cs4(out + (size_t)rg * 448 + j, v);
                }
            }
            __syncthreads();
        }
    }
}

extern "C" void kernel_launch(void* const* d_in, const int* in_sizes, int n_in,
                              void* d_out, int out_size)
{
    const float* x1    = (const float*)d_in[0];
    const float* x2    = (const float*)d_in[1];
    const float* w_ss  = (const float*)d_in[2];
    const float* w_vv0 = (const float*)d_in[3];
    const float* w_sv  = (const float*)d_in[4];
    const float* w_vs  = (const float*)d_in[5];
    const float* w_vv1 = (const float*)d_in[6];
    const float* bias  = (const float*)d_in[7];

    int nrows = in_sizes[0] / 256;
    int ntiles = (nrows + TILE_M - 1) / TILE_M;

    cudaFuncSetAttribute(o3tp_mma10_kernel, cudaFuncAttributeMaxDynamicSharedMemorySize, SM_TOTAL);

    int sm_count = 148;
    cudaDeviceGetAttribute(&sm_count, cudaDevAttrMultiProcessorCount, 0);
    int grid = 3 * sm_count;
    if (grid > ntiles) grid = ntiles;
    if (grid < 1) grid = 1;

    o3tp_mma10_kernel<<<grid, THREADS, SM_TOTAL>>>(
        x1, x2, w_ss, w_vv0, w_sv, w_vs, w_vv1, bias, (float*)d_out, nrows);
}

// round 17
// speedup vs baseline: 2.7235x; 1.6697x over previous
#include <cuda_runtime.h>
#include <cuda_fp16.h>
#include <cstdint>

#define THREADS 256
#define TILE_M 32

// ---- folded constants ----
#define PW0F 0.08838834764831845f   // sqrt(1/128)
#define C0BF 0.05103103630798288f   // PW0/sqrt(3)
#define C1F  0.08838834764831845f   // sqrt(3/128)/sqrt(3) = PW0
#define C2F  0.7071067811865476f    // sqrt(3/64)/sqrt(6)*8 = 1/sqrt(2)

// ---- smem layout (byte offsets), ~80.9 KB -> 2 CTAs / SM ----
// Weights: 5 fp16 tiles [64k x 64n], 128B rows, swizzled. 0=Wss 1=Wvv0 2=Wsv 3=Wvs 4=Wvv1
// A: 6 fp16 buffers [32r x 64k] = 4096B each. ch: 0=PW0*x2s*xs 1=C0B*dot 2=xs 3=a0 4=a1 5=a2
// Stage: 16 rows x 456 fp16 (epilogue half-tile) = 14592B
#define SM_W     0
#define SM_A     40960
#define SM_STG   65536
#define SM_X2    80128      // 32 * float4
#define SM_BIAS  80640      // 64 * f32
#define SM_TOTAL 80896
#define STG_STRIDE 456      // halves; even (4B alignment for __half2 writes)

#define SWZ(o) ((o) ^ (((o) >> 3) & 0x70))

// ================= helpers =================
static __device__ __forceinline__ uint32_t smem_u32(const void* p) {
    uint32_t a;
    asm("{ .reg .u64 t; cvta.to.shared.u64 t, %1; cvt.u32.u64 %0, t; }" : "=r"(a) : "l"(p));
    return a;
}
static __device__ __forceinline__ void ldsm4(uint32_t* r, uint32_t addr) {
    asm volatile("ldmatrix.sync.aligned.m8n8.x4.shared.b16 {%0,%1,%2,%3}, [%4];"
                 : "=r"(r[0]), "=r"(r[1]), "=r"(r[2]), "=r"(r[3]) : "r"(addr));
}
static __device__ __forceinline__ void ldsm4t(uint32_t* r, uint32_t addr) {
    asm volatile("ldmatrix.sync.aligned.m8n8.x4.trans.shared.b16 {%0,%1,%2,%3}, [%4];"
                 : "=r"(r[0]), "=r"(r[1]), "=r"(r[2]), "=r"(r[3]) : "r"(addr));
}
static __device__ __forceinline__ void mma16816h(float* d, const uint32_t* a, uint32_t b0, uint32_t b1) {
    asm volatile("mma.sync.aligned.m16n8k16.row.col.f32.f16.f16.f32 "
                 "{%0,%1,%2,%3}, {%4,%5,%6,%7}, {%8,%9}, {%0,%1,%2,%3};"
                 : "+f"(d[0]), "+f"(d[1]), "+f"(d[2]), "+f"(d[3])
                 : "r"(a[0]), "r"(a[1]), "r"(a[2]), "r"(a[3]), "r"(b0), "r"(b1));
}
static __device__ __forceinline__ void dualmma(float d[2][4], const uint32_t* a, const uint32_t* B) {
    #pragma unroll
    for (int nb = 0; nb < 2; nb++)
        mma16816h(d[nb], a, B[2 * nb], B[2 * nb + 1]);
}
// fp32 pair -> packed fp16 at swizzled offset
static __device__ __forceinline__ void put_h(char* smem, uint32_t base, uint32_t off, float v0, float v1) {
    __half h0 = __float2half_rn(v0);
    __half h1 = __float2half_rn(v1);
    uint32_t hp = (uint32_t)__half_as_ushort(h0) | ((uint32_t)__half_as_ushort(h1) << 16);
    *(uint32_t*)(smem + base + SWZ(off)) = hp;
}
static __device__ __forceinline__ void stg_cs4(float* p, float4 v) {
    asm volatile("st.global.cs.v4.f32 [%0], {%1,%2,%3,%4};"
                 :: "l"(p), "f"(v.x), "f"(v.y), "f"(v.z), "f"(v.w) : "memory");
}

__global__ __launch_bounds__(THREADS, 2)
void o3tp_mma11_kernel(const float* __restrict__ x1, const float* __restrict__ x2,
                       const float* __restrict__ w_ss, const float* __restrict__ w_vv0,
                       const float* __restrict__ w_sv, const float* __restrict__ w_vs,
                       const float* __restrict__ w_vv1, const float* __restrict__ bias,
                       float* __restrict__ out, int nrows)
{
    extern __shared__ char smem[];
    const int tid = threadIdx.x;
    const int lane = tid & 31;
    const int wid = tid >> 5;
    const int rq = wid & 1;        // row block: rows 16*rq .. +16 (of 32)
    const int nh = wid >> 1;       // col block: cols 16*nh .. +16
    const uint32_t smb = smem_u32(smem);

    // ---- weight prep: [k][n] fp16, swizzled ----
    {
        const float* wsrc[5] = { w_ss, w_vv0, w_sv, w_vs, w_vv1 };
        #pragma unroll
        for (int m = 0; m < 5; m++) {
            uint32_t base = SM_W + (uint32_t)m * 8192;
            #pragma unroll
            for (int it = 0; it < 8; it++) {
                int idx = it * THREADS + tid;         // 0..2047
                int k = idx >> 5, np = idx & 31;
                float2 w2 = *(const float2*)(wsrc[m] + k * 64 + 2 * np);
                put_h(smem, base, (uint32_t)(k * 128 + np * 4), w2.x, w2.y);
            }
        }
        if (tid < 64) *(float*)(smem + SM_BIAS + tid * 4) = bias[tid];
    }
    __syncthreads();

    // ---- per-lane constant address pieces ----
    const int t4 = lane >> 3;
    const int arow = 16 * rq + ((t4 & 1) << 3) + (lane & 7);       // 0..31
    const uint32_t a_rb  = (uint32_t)arow * 128;
    const uint32_t a_kx  = (uint32_t)(arow & 7) << 4;
    const uint32_t a_kb0 = (uint32_t)(t4 >> 1) << 4;
    const int brow_l = ((t4 & 1) << 3) + (lane & 7);
    const uint32_t b_cb = (uint32_t)(2 * (16 * nh + ((t4 >> 1) << 3)));
    const uint32_t b_kx = (uint32_t)(lane & 7) << 4;

    const int ntiles = (nrows + TILE_M - 1) / TILE_M;
    const int g = lane >> 2, tq = lane & 3;
    __half* stg = (__half*)(smem + SM_STG);
    const float* bias_s = (const float*)(smem + SM_BIAS);

    for (int tile = blockIdx.x; tile < ntiles; tile += gridDim.x) {
        const int row0 = tile * TILE_M;

        // ---- L2 prefetch next tile's x1 ----
        {
            int tnext = tile + gridDim.x;
            if (tnext < ntiles) {
                int r = tnext * TILE_M + (tid >> 3);
                if (r < nrows) {
                    const float* p = x1 + (size_t)r * 256 + (tid & 7) * 32;
                    asm volatile("prefetch.global.L2 [%0];" :: "l"(p));
                }
            }
        }

        // ---- stage x2 rows ----
        if (tid < 32) {
            int rg = row0 + tid; if (rg >= nrows) rg = nrows - 1;
            *(float4*)(smem + SM_X2 + tid * 16) = *(const float4*)(x2 + (size_t)4 * rg);
        }
        __syncthreads();

        // ---- build 6 A channels, fp16 ----
        #pragma unroll
        for (int it = 0; it < 4; it++) {
            int idx = it * THREADS + tid;            // 0..1023
            int row = idx >> 5, kp = idx & 31;
            int rg = row0 + row; if (rg >= nrows) rg = nrows - 1;
            const float* xr = x1 + (size_t)rg * 256;
            float2 xs = *(const float2*)(xr + 2 * kp);
            float2 f0 = *(const float2*)(xr + 64 + 6 * kp);
            float2 f1 = *(const float2*)(xr + 66 + 6 * kp);
            float2 f2 = *(const float2*)(xr + 68 + 6 * kp);
            float4 q = *(const float4*)(smem + SM_X2 + row * 16);
            uint32_t off = (uint32_t)(row * 128 + kp * 4);
            float sc = PW0F * q.x;
            put_h(smem, SM_A + 0 * 4096, off, sc * xs.x, sc * xs.y);
            float d0 = fmaf(f0.x, q.y, fmaf(f0.y, q.z, f1.x * q.w));
            float d1 = fmaf(f1.y, q.y, fmaf(f2.x, q.z, f2.y * q.w));
            put_h(smem, SM_A + 1 * 4096, off, C0BF * d0, C0BF * d1);
            put_h(smem, SM_A + 2 * 4096, off, xs.x, xs.y);
            put_h(smem, SM_A + 3 * 4096, off, f0.x, f1.y);
            put_h(smem, SM_A + 4 * 4096, off, f0.y, f2.x);
            put_h(smem, SM_A + 5 * 4096, off, f1.x, f2.y);
        }
        __syncthreads();

        // ---- GEMMs: d0=out0(merged) d1=Ysv d2-4=Yv_i(@Wvs) d5-7=Yw_i(@Wvv1) ----
        float d[8][2][4];
        #pragma unroll
        for (int q8 = 0; q8 < 8; q8++)
            #pragma unroll
            for (int nb = 0; nb < 2; nb++)
                #pragma unroll
                for (int e = 0; e < 4; e++) d[q8][nb][e] = 0.0f;

        #pragma unroll
        for (int ks = 0; ks < 4; ks++) {
            const uint32_t a_koff = (32u * ks + a_kb0) ^ a_kx;
            const uint32_t b_base = (uint32_t)(16 * ks + brow_l) * 128 + (b_cb ^ b_kx);
            uint32_t Ax[4], Bh[4];

            ldsm4(Ax, smb + SM_A + 0 * 4096 + a_rb + a_koff);
            ldsm4t(Bh, smb + SM_W + 0 * 8192 + b_base);
            dualmma(d[0], Ax, Bh);

            ldsm4(Ax, smb + SM_A + 1 * 4096 + a_rb + a_koff);
            ldsm4t(Bh, smb + SM_W + 1 * 8192 + b_base);
            dualmma(d[0], Ax, Bh);

            ldsm4(Ax, smb + SM_A + 2 * 4096 + a_rb + a_koff);
            ldsm4t(Bh, smb + SM_W + 2 * 8192 + b_base);
            dualmma(d[1], Ax, Bh);

            uint32_t Vh[4], Wh[4];
            ldsm4t(Vh, smb + SM_W + 3 * 8192 + b_base);
            ldsm4t(Wh, smb + SM_W + 4 * 8192 + b_base);
            #pragma unroll
            for (int j = 0; j < 3; j++) {
                ldsm4(Ax, smb + SM_A + (uint32_t)(3 + j) * 4096 + a_rb + a_koff);
                dualmma(d[2 + j], Ax, Vh);
                dualmma(d[5 + j], Ax, Wh);
            }
        }

        // ---- epilogue in two 16-row halves (fp16 stage writes) ----
        #pragma unroll 1
        for (int half = 0; half < 2; half++) {
            if (rq == half) {
                #pragma unroll
                for (int hh = 0; hh < 2; hh++) {
                    int rl = g + 8 * hh;                           // 0..15 local
                    int rt = 16 * half + rl;                       // 0..31 in tile
                    float4 q = *(const float4*)(smem + SM_X2 + rt * 16);
                    float x2s = q.x, v0 = q.y, v1 = q.z, v2 = q.w;
                    __half* sr = stg + rl * STG_STRIDE;
                    #pragma unroll
                    for (int nt = 0; nt < 2; nt++) {
                        int cc0 = 16 * nh + 8 * nt + 2 * tq;
                        float o0[2], o1[6], o2[6];
                        #pragma unroll
                        for (int e = 0; e < 2; e++) {
                            int ri = 2 * hh + e;
                            float Ysv = d[1][nt][ri];
                            float Yv0 = d[2][nt][ri], Yv1 = d[3][nt][ri], Yv2 = d[4][nt][ri];
                            float Yw0 = d[5][nt][ri], Yw1 = d[6][nt][ri], Yw2 = d[7][nt][ri];
                            o0[e] = d[0][nt][ri] + bias_s[cc0 + e];
                            o1[3 * e + 0] = C1F * fmaf(v0, Ysv, x2s * Yv0);
                            o1[3 * e + 1] = C1F * fmaf(v1, Ysv, x2s * Yv1);
                            o1[3 * e + 2] = C1F * fmaf(v2, Ysv, x2s * Yv2);
                            o2[3 * e + 0] = C2F * (Yw1 * v2 - Yw2 * v1);
                            o2[3 * e + 1] = C2F * (Yw2 * v0 - Yw0 * v2);
                            o2[3 * e + 2] = C2F * (Yw0 * v1 - Yw1 * v0);
                        }
                        *(__half2*)(sr + cc0) = __floats2half2_rn(o0[0], o0[1]);
                        __half* p1 = sr + 64 + 3 * cc0;
                        *(__half2*)(p1 + 0) = __floats2half2_rn(o1[0], o1[1]);
                        *(__half2*)(p1 + 2) = __floats2half2_rn(o1[2], o1[3]);
                        *(__half2*)(p1 + 4) = __floats2half2_rn(o1[4], o1[5]);
                        __half* p2 = sr + 256 + 3 * cc0;
                        *(__half2*)(p2 + 0) = __floats2half2_rn(o2[0], o2[1]);
                        *(__half2*)(p2 + 2) = __floats2half2_rn(o2[2], o2[3]);
                        *(__half2*)(p2 + 4) = __floats2half2_rn(o2[4], o2[5]);
                    }
                }
            }
            __syncthreads();
            // coalesced streaming copy-out: 16 rows x 448 f32 (read fp16, store fp32)
            #pragma unroll
            for (int i = 0; i < 7; i++) {
                int f = i * THREADS + tid;               // < 1792
                int r = f / 112, j = (f % 112) * 4;
                const __half2* hp = (const __half2*)(stg + r * STG_STRIDE + j);
                float2 a = __half22float2(hp[0]);
                float2 b = __half22float2(hp[1]);
                int rg = row0 + 16 * half + r;
                if (rg < nrows)
                    stg_cs4(out + (size_t)rg * 448 + j, make_float4(a.x, a.y, b.x, b.y));
            }
            __syncthreads();
        }
    }
}

extern "C" void kernel_launch(void* const* d_in, const int* in_sizes, int n_in,
                              void* d_out, int out_size)
{
    const float* x1    = (const float*)d_in[0];
    const float* x2    = (const float*)d_in[1];
    const float* w_ss  = (const float*)d_in[2];
    const float* w_vv0 = (const float*)d_in[3];
    const float* w_sv  = (const float*)d_in[4];
    const float* w_vs  = (const float*)d_in[5];
    const float* w_vv1 = (const float*)d_in[6];
    const float* bias  = (const float*)d_in[7];

    int nrows = in_sizes[0] / 256;
    int ntiles = (nrows + TILE_M - 1) / TILE_M;

    cudaFuncSetAttribute(o3tp_mma11_kernel, cudaFuncAttributeMaxDynamicSharedMemorySize, SM_TOTAL);

    int sm_count = 148;
    cudaDeviceGetAttribute(&sm_count, cudaDevAttrMultiProcessorCount, 0);
    int grid = 2 * sm_count;
    if (grid > ntiles) grid = ntiles;
    if (grid < 1) grid = 1;

    o3tp_mma11_kernel<<<grid, THREADS, SM_TOTAL>>>(
        x1, x2, w_ss, w_vv0, w_sv, w_vs, w_vv1, bias, (float*)d_out, nrows);
}